// round 1
// baseline (speedup 1.0000x reference)
#include <cuda_runtime.h>
#include <math.h>

#define HIDDEN 128
#define MIX 8
#define MAXN 10000

// Scratch (allocation-free rule: __device__ globals)
__device__ __align__(16) float g_T[MAXN * MIX];                      // per-node hyper weights
__device__ __align__(16) float g_agg[(size_t)MAXN * HIDDEN * MIX];   // 40.96 MB accumulator
__device__ int g_is64;                                               // edge_index dtype flag

__device__ __forceinline__ float gelu_exact(float x) {
    return 0.5f * x * (1.0f + erff(x * 0.70710678118654752f));
}

// Detect int64 vs int32 edge_index: node ids < 10000, so int64 high words are 0.
// For int32, odd 32-bit words are random node ids in [0,10000) — P(all 64 zero) ~ 0.
__global__ void detect_idx_kernel(const unsigned int* __restrict__ w) {
    if (blockIdx.x == 0 && threadIdx.x == 0) {
        int is64 = 1;
        #pragma unroll
        for (int i = 0; i < 64; i++)
            if (w[2 * i + 1] != 0u) is64 = 0;
        g_is64 = is64;
    }
}

__device__ __forceinline__ void load_edge(const void* ei, int e, int E, int& s, int& d) {
    if (g_is64) {
        const long long* p = (const long long*)ei;
        s = (int)p[e];
        d = (int)p[(size_t)E + e];
    } else {
        const int* p = (const int*)ei;
        s = p[e];
        d = p[(size_t)E + e];
    }
}

__global__ void zero_agg_kernel(int total4) {
    float4* p = (float4*)g_agg;
    float4 z = make_float4(0.f, 0.f, 0.f, 0.f);
    int stride = gridDim.x * blockDim.x;
    for (int i = blockIdx.x * blockDim.x + threadIdx.x; i < total4; i += stride)
        p[i] = z;
}

// T[n,m] = dot( gelu( X[n,:] @ W_A[h,:] for each h ), W_B[m,:] )
// 16 nodes per block of 128 threads; each thread owns one hidden column h.
__global__ void compute_T_kernel(const float* __restrict__ X,
                                 const float* __restrict__ WA,
                                 const float* __restrict__ WB,
                                 int N) {
    __shared__ float xs[16][HIDDEN];
    __shared__ float gs[16][HIDDEN];
    int t = threadIdx.x;
    int base = blockIdx.x * 16;

    #pragma unroll
    for (int r = 0; r < 16; r++) {
        int n = base + r;
        xs[r][t] = (n < N) ? X[(size_t)n * HIDDEN + t] : 0.f;
    }
    __syncthreads();

    const float* wa = WA + (size_t)t * HIDDEN;  // row h=t of W_A
    float acc[16];
    #pragma unroll
    for (int r = 0; r < 16; r++) acc[r] = 0.f;
    for (int k = 0; k < HIDDEN; k++) {
        float w = __ldg(wa + k);
        #pragma unroll
        for (int r = 0; r < 16; r++) acc[r] += xs[r][k] * w;
    }
    #pragma unroll
    for (int r = 0; r < 16; r++) gs[r][t] = gelu_exact(acc[r]);
    __syncthreads();

    // 128 threads -> (r = t/8 in [0,16), m = t%8)
    int r = t >> 3, m = t & 7;
    int n = base + r;
    if (n < N) {
        const float* wb = WB + (size_t)m * HIDDEN;
        float a = 0.f;
        for (int k = 0; k < HIDDEN; k++) a += gs[r][k] * __ldg(wb + k);
        g_T[(size_t)n * MIX + m] = a;
    }
}

__device__ __forceinline__ void red_add_f32x4(float* addr, float4 v) {
#if __CUDA_ARCH__ >= 900
    asm volatile("red.global.add.v4.f32 [%0], {%1,%2,%3,%4};"
                 :: "l"(addr), "f"(v.x), "f"(v.y), "f"(v.z), "f"(v.w)
                 : "memory");
#else
    atomicAdd(addr + 0, v.x);
    atomicAdd(addr + 1, v.y);
    atomicAdd(addr + 2, v.z);
    atomicAdd(addr + 3, v.w);
#endif
}

// One warp per edge: agg[d, h, m] += X[s,h] * T[s,m]
__global__ void scatter_kernel(const float* __restrict__ X, const void* __restrict__ ei, int E) {
    int e = (blockIdx.x * blockDim.x + threadIdx.x) >> 5;
    if (e >= E) return;
    int lane = threadIdx.x & 31;

    int s, d;
    load_edge(ei, e, E, s, d);

    float tm[MIX];
    const float* T = g_T + (size_t)s * MIX;
    #pragma unroll
    for (int m = 0; m < MIX; m++) tm[m] = __ldg(T + m);

    float* aggd = g_agg + (size_t)d * HIDDEN * MIX;
    const float* xrow = X + (size_t)s * HIDDEN;

    #pragma unroll
    for (int j = 0; j < 4; j++) {
        int h = lane + 32 * j;
        float x = __ldg(xrow + h);
        float4 v0 = make_float4(x * tm[0], x * tm[1], x * tm[2], x * tm[3]);
        float4 v1 = make_float4(x * tm[4], x * tm[5], x * tm[6], x * tm[7]);
        red_add_f32x4(aggd + (size_t)h * MIX, v0);
        red_add_f32x4(aggd + (size_t)h * MIX + 4, v1);
    }
}

__global__ void gelu_agg_kernel(int total4) {
    float4* p = (float4*)g_agg;
    int stride = gridDim.x * blockDim.x;
    for (int i = blockIdx.x * blockDim.x + threadIdx.x; i < total4; i += stride) {
        float4 v = p[i];
        v.x = gelu_exact(v.x);
        v.y = gelu_exact(v.y);
        v.z = gelu_exact(v.z);
        v.w = gelu_exact(v.w);
        p[i] = v;
    }
}

// One warp per edge: out[e,h] = sum_m gelu(agg)[d,h,m] * T[s,m]
__global__ void gather_kernel(const void* __restrict__ ei, float* __restrict__ out, int E) {
    int e = (blockIdx.x * blockDim.x + threadIdx.x) >> 5;
    if (e >= E) return;
    int lane = threadIdx.x & 31;

    int s, d;
    load_edge(ei, e, E, s, d);

    float tm[MIX];
    const float* T = g_T + (size_t)s * MIX;
    #pragma unroll
    for (int m = 0; m < MIX; m++) tm[m] = __ldg(T + m);

    const float4* aggd = (const float4*)(g_agg + (size_t)d * HIDDEN * MIX);

    #pragma unroll
    for (int j = 0; j < 4; j++) {
        int h = lane + 32 * j;
        float4 a0 = aggd[2 * h];
        float4 a1 = aggd[2 * h + 1];
        float r = a0.x * tm[0] + a0.y * tm[1] + a0.z * tm[2] + a0.w * tm[3]
                + a1.x * tm[4] + a1.y * tm[5] + a1.z * tm[6] + a1.w * tm[7];
        out[(size_t)e * HIDDEN + h] = r;
    }
}

// Optional tail: src/dst appended as floats (if the harness compares the full tuple)
__global__ void tail_kernel(const void* __restrict__ ei, float* __restrict__ out, int E) {
    int e = blockIdx.x * blockDim.x + threadIdx.x;
    if (e >= E) return;
    int s, d;
    load_edge(ei, e, E, s, d);
    out[(size_t)E * HIDDEN + e] = (float)s;
    out[(size_t)E * HIDDEN + E + e] = (float)d;
}

extern "C" void kernel_launch(void* const* d_in, const int* in_sizes, int n_in,
                              void* d_out, int out_size) {
    const float* X  = (const float*)d_in[0];
    const float* WA = (const float*)d_in[1];
    const float* WB = (const float*)d_in[2];
    const void*  ei = d_in[3];

    int N = in_sizes[0] / HIDDEN;   // 10000
    int E = in_sizes[3] / 2;        // 320000
    float* out = (float*)d_out;

    detect_idx_kernel<<<1, 32>>>((const unsigned int*)ei);

    int total4 = (N * HIDDEN * MIX) / 4;
    zero_agg_kernel<<<2048, 256>>>(total4);

    compute_T_kernel<<<(N + 15) / 16, 128>>>(X, WA, WB, N);

    int edge_blocks = (E + 7) / 8;  // 8 warps (edges) per 256-thread block
    scatter_kernel<<<edge_blocks, 256>>>(X, ei, E);

    gelu_agg_kernel<<<2048, 256>>>(total4);

    gather_kernel<<<edge_blocks, 256>>>(ei, out, E);

    if ((long long)out_size >= (long long)E * (HIDDEN + 2)) {
        tail_kernel<<<(E + 255) / 256, 256>>>(ei, out, E);
    }
}

// round 2
// speedup vs baseline: 2.2821x; 2.2821x over previous
#include <cuda_runtime.h>
#include <math.h>

#define HIDDEN 128
#define MIX 8
#define MAXN 10000
#define MAXE 512000

// Scratch (allocation-free rule: __device__ globals)
__device__ __align__(16) float g_T[MAXN * MIX];     // per-node hyper weights
__device__ int g_count[MAXN];                        // histogram / cursor pair
__device__ int g_cursor[MAXN];
__device__ int g_offsets[MAXN + 1];
__device__ int g_src_sorted[MAXE];
__device__ int g_eid_sorted[MAXE];
__device__ int g_is64;                               // edge_index dtype flag

__device__ __forceinline__ float gelu_exact(float x) {
    return 0.5f * x * (1.0f + erff(x * 0.70710678118654752f));
}

__global__ void detect_idx_kernel(const unsigned int* __restrict__ w) {
    if (blockIdx.x == 0 && threadIdx.x == 0) {
        int is64 = 1;
        #pragma unroll
        for (int i = 0; i < 64; i++)
            if (w[2 * i + 1] != 0u) is64 = 0;
        g_is64 = is64;
    }
}

__device__ __forceinline__ void load_edge(const void* ei, int e, int E, int& s, int& d) {
    if (g_is64) {
        const long long* p = (const long long*)ei;
        s = (int)p[e];
        d = (int)p[(size_t)E + e];
    } else {
        const int* p = (const int*)ei;
        s = p[e];
        d = p[(size_t)E + e];
    }
}

__global__ void zero_counts_kernel(int N) {
    int i = blockIdx.x * blockDim.x + threadIdx.x;
    if (i < N) { g_count[i] = 0; g_cursor[i] = 0; }
}

__global__ void hist_kernel(const void* __restrict__ ei, int E) {
    int e = blockIdx.x * blockDim.x + threadIdx.x;
    if (e >= E) return;
    int s, d;
    load_edge(ei, e, E, s, d);
    atomicAdd(&g_count[d], 1);
}

#define SCAN_T 1024
__global__ void scan_kernel(int N) {
    __shared__ int sums[SCAN_T];
    int t = threadIdx.x;
    int per = (N + SCAN_T - 1) / SCAN_T;
    int beg = t * per;
    int end = min(beg + per, N);
    int local = 0;
    for (int i = beg; i < end; i++) local += g_count[i];
    sums[t] = local;
    __syncthreads();
    for (int off = 1; off < SCAN_T; off <<= 1) {
        int v = (t >= off) ? sums[t - off] : 0;
        __syncthreads();
        sums[t] += v;
        __syncthreads();
    }
    int run = (t == 0) ? 0 : sums[t - 1];
    for (int i = beg; i < end; i++) { g_offsets[i] = run; run += g_count[i]; }
    if (t == SCAN_T - 1) g_offsets[N] = run;
}

__global__ void reorder_kernel(const void* __restrict__ ei, int E) {
    int e = blockIdx.x * blockDim.x + threadIdx.x;
    if (e >= E) return;
    int s, d;
    load_edge(ei, e, E, s, d);
    int pos = g_offsets[d] + atomicAdd(&g_cursor[d], 1);
    g_src_sorted[pos] = s;
    g_eid_sorted[pos] = e;
}

// T[n,m] = dot( gelu( X[n,:] @ W_A[h,:] ), W_B[m,:] )
__global__ void compute_T_kernel(const float* __restrict__ X,
                                 const float* __restrict__ WA,
                                 const float* __restrict__ WB,
                                 int N) {
    __shared__ float xs[16][HIDDEN];
    __shared__ float gs[16][HIDDEN];
    int t = threadIdx.x;
    int base = blockIdx.x * 16;

    #pragma unroll
    for (int r = 0; r < 16; r++) {
        int n = base + r;
        xs[r][t] = (n < N) ? X[(size_t)n * HIDDEN + t] : 0.f;
    }
    __syncthreads();

    const float* wa = WA + (size_t)t * HIDDEN;
    float acc[16];
    #pragma unroll
    for (int r = 0; r < 16; r++) acc[r] = 0.f;
    for (int k = 0; k < HIDDEN; k++) {
        float w = __ldg(wa + k);
        #pragma unroll
        for (int r = 0; r < 16; r++) acc[r] += xs[r][k] * w;
    }
    #pragma unroll
    for (int r = 0; r < 16; r++) gs[r][t] = gelu_exact(acc[r]);
    __syncthreads();

    int r = t >> 3, m = t & 7;
    int n = base + r;
    if (n < N) {
        const float* wb = WB + (size_t)m * HIDDEN;
        float a = 0.f;
        for (int k = 0; k < HIDDEN; k++) a += gs[r][k] * __ldg(wb + k);
        g_T[(size_t)n * MIX + m] = a;
    }
}

// One CTA per dst node d. 256 threads.
//  Phase A: acc[h][m] += X[s,h]*T[s,m] over all edges with this dst (registers).
//  Phase B: gelu, stage to padded smem.
//  Phase C: for each edge e (src s) of d: out[e,h] = sum_m agg[h][m]*T[s,m].
#define CHUNK 256
__global__ void __launch_bounds__(256, 6) fused_kernel(const float* __restrict__ X,
                                                       float* __restrict__ out) {
    int d = blockIdx.x;
    int beg = g_offsets[d];
    int end = g_offsets[d + 1];
    if (beg == end) return;

    __shared__ int ss[CHUNK];
    __shared__ int es[CHUNK];
    __shared__ float agg[HIDDEN * 9];   // stride-9 pad: conflict-free

    int t = threadIdx.x;
    int h = t & 127;
    int mg = (t >> 7) * 4;              // m-group: 0 or 4

    float a0 = 0.f, a1 = 0.f, a2 = 0.f, a3 = 0.f;

    // Phase A: accumulate
    for (int base = beg; base < end; base += CHUNK) {
        int n = min(CHUNK, end - base);
        if (t < n) ss[t] = g_src_sorted[base + t];
        __syncthreads();
        for (int i = 0; i < n; i++) {
            int s = ss[i];
            float x = __ldg(X + (size_t)s * HIDDEN + h);
            float4 tm = *(const float4*)(g_T + (size_t)s * MIX + mg);
            a0 = fmaf(x, tm.x, a0);
            a1 = fmaf(x, tm.y, a1);
            a2 = fmaf(x, tm.z, a2);
            a3 = fmaf(x, tm.w, a3);
        }
        __syncthreads();
    }

    // Phase B: gelu + stage
    agg[h * 9 + mg + 0] = gelu_exact(a0);
    agg[h * 9 + mg + 1] = gelu_exact(a1);
    agg[h * 9 + mg + 2] = gelu_exact(a2);
    agg[h * 9 + mg + 3] = gelu_exact(a3);
    __syncthreads();

    // Phase C: per-edge contraction, 2 edges in flight (256 = 2 x 128)
    int le = t >> 7;                    // 0 or 1
    for (int base = beg; base < end; base += CHUNK) {
        int n = min(CHUNK, end - base);
        if (t < n) {
            ss[t] = g_src_sorted[base + t];
            es[t] = g_eid_sorted[base + t];
        }
        __syncthreads();
        for (int i = le; i < n; i += 2) {
            int s = ss[i];
            int e = es[i];
            const float* T = g_T + (size_t)s * MIX;
            float r = 0.f;
            #pragma unroll
            for (int m = 0; m < MIX; m++)
                r = fmaf(agg[h * 9 + m], __ldg(T + m), r);
            out[(size_t)e * HIDDEN + h] = r;
        }
        __syncthreads();
    }
}

// Optional tail: src/dst appended as floats (full-tuple output case)
__global__ void tail_kernel(const void* __restrict__ ei, float* __restrict__ out, int E) {
    int e = blockIdx.x * blockDim.x + threadIdx.x;
    if (e >= E) return;
    int s, d;
    load_edge(ei, e, E, s, d);
    out[(size_t)E * HIDDEN + e] = (float)s;
    out[(size_t)E * HIDDEN + E + e] = (float)d;
}

extern "C" void kernel_launch(void* const* d_in, const int* in_sizes, int n_in,
                              void* d_out, int out_size) {
    const float* X  = (const float*)d_in[0];
    const float* WA = (const float*)d_in[1];
    const float* WB = (const float*)d_in[2];
    const void*  ei = d_in[3];

    int N = in_sizes[0] / HIDDEN;   // 10000
    int E = in_sizes[3] / 2;        // 320000
    float* out = (float*)d_out;

    detect_idx_kernel<<<1, 32>>>((const unsigned int*)ei);
    zero_counts_kernel<<<(N + 255) / 256, 256>>>(N);
    hist_kernel<<<(E + 255) / 256, 256>>>(ei, E);
    scan_kernel<<<1, SCAN_T>>>(N);
    reorder_kernel<<<(E + 255) / 256, 256>>>(ei, E);
    compute_T_kernel<<<(N + 15) / 16, 128>>>(X, WA, WB, N);
    fused_kernel<<<N, 256>>>(X, out);

    if ((long long)out_size >= (long long)E * (HIDDEN + 2)) {
        tail_kernel<<<(E + 255) / 256, 256>>>(ei, out, E);
    }
}

// round 3
// speedup vs baseline: 2.5389x; 1.1125x over previous
#include <cuda_runtime.h>
#include <math.h>

#define HIDDEN 128
#define MIX 8
#define MAXN 10000
#define MAXE 512000

// Scratch (allocation-free rule: __device__ globals)
__device__ __align__(16) float g_T[MAXN * MIX];      // per-node hyper weights
__device__ int g_count[MAXN];
__device__ int g_cursor[MAXN];
__device__ int g_offsets[MAXN + 1];
__device__ __align__(8) int2 g_se[MAXE];             // sorted (src, edge_id)
__device__ int g_is64;

__device__ __forceinline__ float gelu_exact(float x) {
    return 0.5f * x * (1.0f + erff(x * 0.70710678118654752f));
}

__device__ __forceinline__ void load_edge(const void* ei, int e, int E, int& s, int& d) {
    if (g_is64) {
        const long long* p = (const long long*)ei;
        s = (int)p[e];
        d = (int)p[(size_t)E + e];
    } else {
        const int* p = (const int*)ei;
        s = p[e];
        d = p[(size_t)E + e];
    }
}

// Zero counters + detect int64-vs-int32 edge_index (node ids < N => int64 high words 0)
__global__ void prep_kernel(const unsigned int* __restrict__ w, int N) {
    int i = blockIdx.x * blockDim.x + threadIdx.x;
    if (i < N) { g_count[i] = 0; g_cursor[i] = 0; }
    if (i == 0) {
        int is64 = 1;
        #pragma unroll
        for (int k = 0; k < 64; k++)
            if (w[2 * k + 1] != 0u) is64 = 0;
        g_is64 = is64;
    }
}

__global__ void hist_kernel(const void* __restrict__ ei, int E) {
    int e = blockIdx.x * blockDim.x + threadIdx.x;
    if (e >= E) return;
    int s, d;
    load_edge(ei, e, E, s, d);
    atomicAdd(&g_count[d], 1);
}

#define SCAN_T 1024
__global__ void scan_kernel(int N) {
    __shared__ int wsum[32];
    int t = threadIdx.x;
    int lane = t & 31, wid = t >> 5;
    int per = (N + SCAN_T - 1) / SCAN_T;
    int beg = t * per;
    int end = min(beg + per, N);

    int local = 0;
    for (int i = beg; i < end; i++) local += g_count[i];

    int v = local;
    #pragma unroll
    for (int off = 1; off < 32; off <<= 1) {
        int u = __shfl_up_sync(0xffffffffu, v, off);
        if (lane >= off) v += u;
    }
    if (lane == 31) wsum[wid] = v;
    __syncthreads();
    if (wid == 0) {
        int wv = wsum[lane];
        #pragma unroll
        for (int off = 1; off < 32; off <<= 1) {
            int u = __shfl_up_sync(0xffffffffu, wv, off);
            if (lane >= off) wv += u;
        }
        wsum[lane] = wv;
    }
    __syncthreads();

    int warp_excl = (wid == 0) ? 0 : wsum[wid - 1];
    int run = warp_excl + (v - local);   // exclusive prefix for this thread
    for (int i = beg; i < end; i++) { g_offsets[i] = run; run += g_count[i]; }
    if (t == SCAN_T - 1) g_offsets[N] = run;
}

__global__ void reorder_kernel(const void* __restrict__ ei, int E) {
    int e = blockIdx.x * blockDim.x + threadIdx.x;
    if (e >= E) return;
    int s, d;
    load_edge(ei, e, E, s, d);
    int pos = g_offsets[d] + atomicAdd(&g_cursor[d], 1);
    g_se[pos] = make_int2(s, e);
}

// T[n,m] = dot( gelu( X[n,:] @ W_A^T ), W_B[m,:] )
__global__ void compute_T_kernel(const float* __restrict__ X,
                                 const float* __restrict__ WA,
                                 const float* __restrict__ WB,
                                 int N) {
    __shared__ float xs[16][HIDDEN];
    __shared__ float gs[16][HIDDEN];
    int t = threadIdx.x;
    int base = blockIdx.x * 16;

    #pragma unroll
    for (int r = 0; r < 16; r++) {
        int n = base + r;
        xs[r][t] = (n < N) ? X[(size_t)n * HIDDEN + t] : 0.f;
    }
    __syncthreads();

    const float* wa = WA + (size_t)t * HIDDEN;
    float acc[16];
    #pragma unroll
    for (int r = 0; r < 16; r++) acc[r] = 0.f;
    for (int k = 0; k < HIDDEN; k++) {
        float w = __ldg(wa + k);
        #pragma unroll
        for (int r = 0; r < 16; r++) acc[r] += xs[r][k] * w;
    }
    #pragma unroll
    for (int r = 0; r < 16; r++) gs[r][t] = gelu_exact(acc[r]);
    __syncthreads();

    int r = t >> 3, m = t & 7;
    int n = base + r;
    if (n < N) {
        const float* wb = WB + (size_t)m * HIDDEN;
        float a = 0.f;
        for (int k = 0; k < HIDDEN; k++) a += gs[r][k] * __ldg(wb + k);
        g_T[(size_t)n * MIX + m] = a;
    }
}

// One CTA (128 threads) per dst node. Thread t owns h=t and all 8 mix accumulators.
// No shared memory, no barriers.
__global__ void __launch_bounds__(128, 12)
fused_kernel(const float* __restrict__ X, float* __restrict__ out) {
    int d = blockIdx.x;
    int beg = g_offsets[d];
    int end = g_offsets[d + 1];
    if (beg == end) return;

    int h = threadIdx.x;
    const float* Xh = X + h;

    float a[8];
    #pragma unroll
    for (int m = 0; m < 8; m++) a[m] = 0.f;

    // Phase A: agg[d,h,:] += X[s,h] * T[s,:]
    for (int i = beg; i < end; i++) {
        int s = __ldg(&g_se[i].x);                         // uniform, L1-hit
        float x = __ldg(Xh + (size_t)s * HIDDEN);          // coalesced 128B/warp
        float4 t0 = __ldg((const float4*)(g_T + (size_t)s * MIX));      // uniform bcast
        float4 t1 = __ldg((const float4*)(g_T + (size_t)s * MIX) + 1);
        a[0] = fmaf(x, t0.x, a[0]);
        a[1] = fmaf(x, t0.y, a[1]);
        a[2] = fmaf(x, t0.z, a[2]);
        a[3] = fmaf(x, t0.w, a[3]);
        a[4] = fmaf(x, t1.x, a[4]);
        a[5] = fmaf(x, t1.y, a[5]);
        a[6] = fmaf(x, t1.z, a[6]);
        a[7] = fmaf(x, t1.w, a[7]);
    }

    // Phase B: gelu in registers
    #pragma unroll
    for (int m = 0; m < 8; m++) a[m] = gelu_exact(a[m]);

    // Phase C: out[e,h] = sum_m agg[d,h,m] * T[s_e,m]
    for (int i = beg; i < end; i++) {
        int2 p = __ldg(&g_se[i]);                          // (src, eid), uniform
        float4 t0 = __ldg((const float4*)(g_T + (size_t)p.x * MIX));
        float4 t1 = __ldg((const float4*)(g_T + (size_t)p.x * MIX) + 1);
        float r = fmaf(a[0], t0.x,
                  fmaf(a[1], t0.y,
                  fmaf(a[2], t0.z,
                  fmaf(a[3], t0.w,
                  fmaf(a[4], t1.x,
                  fmaf(a[5], t1.y,
                  fmaf(a[6], t1.z, a[7] * t1.w)))))));
        out[(size_t)p.y * HIDDEN + h] = r;                 // coalesced 128B/warp
    }
}

// Optional tail: src/dst appended as floats (full-tuple output case)
__global__ void tail_kernel(const void* __restrict__ ei, float* __restrict__ out, int E) {
    int e = blockIdx.x * blockDim.x + threadIdx.x;
    if (e >= E) return;
    int s, d;
    load_edge(ei, e, E, s, d);
    out[(size_t)E * HIDDEN + e] = (float)s;
    out[(size_t)E * HIDDEN + E + e] = (float)d;
}

extern "C" void kernel_launch(void* const* d_in, const int* in_sizes, int n_in,
                              void* d_out, int out_size) {
    const float* X  = (const float*)d_in[0];
    const float* WA = (const float*)d_in[1];
    const float* WB = (const float*)d_in[2];
    const void*  ei = d_in[3];

    int N = in_sizes[0] / HIDDEN;   // 10000
    int E = in_sizes[3] / 2;        // 320000
    float* out = (float*)d_out;

    prep_kernel<<<(N + 255) / 256, 256>>>((const unsigned int*)ei, N);
    hist_kernel<<<(E + 255) / 256, 256>>>(ei, E);
    scan_kernel<<<1, SCAN_T>>>(N);
    reorder_kernel<<<(E + 255) / 256, 256>>>(ei, E);
    compute_T_kernel<<<(N + 15) / 16, 128>>>(X, WA, WB, N);
    fused_kernel<<<N, 128>>>(X, out);

    if ((long long)out_size >= (long long)E * (HIDDEN + 2)) {
        tail_kernel<<<(E + 255) / 256, 256>>>(ei, out, E);
    }
}

// round 4
// speedup vs baseline: 3.1443x; 1.2385x over previous
#include <cuda_runtime.h>
#include <math.h>

#define HIDDEN 128
#define MIX 8
#define MAXN 10000
#define MAXE 512000

// Scratch (allocation-free rule: __device__ globals)
__device__ __align__(16) float g_T[MAXN * MIX];      // per-node hyper weights
__device__ int g_count[MAXN];
__device__ int g_cursor[MAXN];
__device__ int g_offsets[MAXN + 1];
__device__ __align__(8) int2 g_se[MAXE];             // sorted (src, edge_id)
__device__ int g_is64;

__device__ __forceinline__ float gelu_exact(float x) {
    return 0.5f * x * (1.0f + erff(x * 0.70710678118654752f));
}

__device__ __forceinline__ void load_edge(const void* ei, int e, int E, int& s, int& d) {
    if (g_is64) {
        const long long* p = (const long long*)ei;
        s = (int)p[e];
        d = (int)p[(size_t)E + e];
    } else {
        const int* p = (const int*)ei;
        s = p[e];
        d = p[(size_t)E + e];
    }
}

// Zero counters + detect int64-vs-int32 edge_index (node ids < N => int64 high words 0)
__global__ void prep_kernel(const unsigned int* __restrict__ w, int N) {
    int i = blockIdx.x * blockDim.x + threadIdx.x;
    if (i < N) { g_count[i] = 0; g_cursor[i] = 0; }
    if (i == 0) {
        int is64 = 1;
        #pragma unroll
        for (int k = 0; k < 64; k++)
            if (w[2 * k + 1] != 0u) is64 = 0;
        g_is64 = is64;
    }
}

__global__ void hist_kernel(const void* __restrict__ ei, int E) {
    int e = blockIdx.x * blockDim.x + threadIdx.x;
    if (e >= E) return;
    int s, d;
    load_edge(ei, e, E, s, d);
    atomicAdd(&g_count[d], 1);
}

#define SCAN_T 1024
__global__ void scan_kernel(int N) {
    __shared__ int wsum[32];
    int t = threadIdx.x;
    int lane = t & 31, wid = t >> 5;
    int per = (N + SCAN_T - 1) / SCAN_T;
    int beg = t * per;
    int end = min(beg + per, N);

    int local = 0;
    for (int i = beg; i < end; i++) local += g_count[i];

    int v = local;
    #pragma unroll
    for (int off = 1; off < 32; off <<= 1) {
        int u = __shfl_up_sync(0xffffffffu, v, off);
        if (lane >= off) v += u;
    }
    if (lane == 31) wsum[wid] = v;
    __syncthreads();
    if (wid == 0) {
        int wv = wsum[lane];
        #pragma unroll
        for (int off = 1; off < 32; off <<= 1) {
            int u = __shfl_up_sync(0xffffffffu, wv, off);
            if (lane >= off) wv += u;
        }
        wsum[lane] = wv;
    }
    __syncthreads();

    int warp_excl = (wid == 0) ? 0 : wsum[wid - 1];
    int run = warp_excl + (v - local);   // exclusive prefix for this thread
    for (int i = beg; i < end; i++) { g_offsets[i] = run; run += g_count[i]; }
    if (t == SCAN_T - 1) g_offsets[N] = run;
}

__global__ void reorder_kernel(const void* __restrict__ ei, int E) {
    int e = blockIdx.x * blockDim.x + threadIdx.x;
    if (e >= E) return;
    int s, d;
    load_edge(ei, e, E, s, d);
    int pos = g_offsets[d] + atomicAdd(&g_cursor[d], 1);
    g_se[pos] = make_int2(s, e);
}

// T[n,m] = dot( gelu( X[n,:] @ W_A^T ), W_B[m,:] )
__global__ void compute_T_kernel(const float* __restrict__ X,
                                 const float* __restrict__ WA,
                                 const float* __restrict__ WB,
                                 int N) {
    __shared__ float xs[16][HIDDEN];
    __shared__ float gs[16][HIDDEN];
    int t = threadIdx.x;
    int base = blockIdx.x * 16;

    #pragma unroll
    for (int r = 0; r < 16; r++) {
        int n = base + r;
        xs[r][t] = (n < N) ? X[(size_t)n * HIDDEN + t] : 0.f;
    }
    __syncthreads();

    const float* wa = WA + (size_t)t * HIDDEN;
    float acc[16];
    #pragma unroll
    for (int r = 0; r < 16; r++) acc[r] = 0.f;
    for (int k = 0; k < HIDDEN; k++) {
        float w = __ldg(wa + k);
        #pragma unroll
        for (int r = 0; r < 16; r++) acc[r] += xs[r][k] * w;
    }
    #pragma unroll
    for (int r = 0; r < 16; r++) gs[r][t] = gelu_exact(acc[r]);
    __syncthreads();

    int r = t >> 3, m = t & 7;
    int n = base + r;
    if (n < N) {
        const float* wb = WB + (size_t)m * HIDDEN;
        float a = 0.f;
        for (int k = 0; k < HIDDEN; k++) a += gs[r][k] * __ldg(wb + k);
        g_T[(size_t)n * MIX + m] = a;
    }
}

// ONE WARP per dst node. Lane l owns h = 4l..4l+3 (float4), all 8 mix accs in regs.
// Per edge per warp: Phase A = 3 LDG + 32 FMA/thread, Phase C = 3 LDG + 1 STG.128.
// No shared memory, no barriers.
#define WPB 8
__global__ void __launch_bounds__(32 * WPB, 4)
fused_kernel(const float* __restrict__ X, float* __restrict__ out, int N) {
    int d = blockIdx.x * WPB + (threadIdx.x >> 5);
    if (d >= N) return;
    int lane = threadIdx.x & 31;

    int beg = g_offsets[d];
    int end = g_offsets[d + 1];
    if (beg == end) return;

    float a0[8], a1[8], a2[8], a3[8];
    #pragma unroll
    for (int m = 0; m < 8; m++) { a0[m] = 0.f; a1[m] = 0.f; a2[m] = 0.f; a3[m] = 0.f; }

    // Phase A: agg[d, 4l..4l+3, m] += X[s, 4l..4l+3] * T[s, m]
    for (int i = beg; i < end; i++) {
        int s = __ldg(&g_se[i].x);
        float4 x = __ldg((const float4*)(X + (size_t)s * HIDDEN) + lane);
        const float4* Tp = (const float4*)(g_T + (size_t)s * MIX);
        float4 t0 = __ldg(Tp);
        float4 t1 = __ldg(Tp + 1);
        float t[8] = {t0.x, t0.y, t0.z, t0.w, t1.x, t1.y, t1.z, t1.w};
        #pragma unroll
        for (int m = 0; m < 8; m++) {
            a0[m] = fmaf(x.x, t[m], a0[m]);
            a1[m] = fmaf(x.y, t[m], a1[m]);
            a2[m] = fmaf(x.z, t[m], a2[m]);
            a3[m] = fmaf(x.w, t[m], a3[m]);
        }
    }

    // Phase B: gelu in registers
    #pragma unroll
    for (int m = 0; m < 8; m++) {
        a0[m] = gelu_exact(a0[m]);
        a1[m] = gelu_exact(a1[m]);
        a2[m] = gelu_exact(a2[m]);
        a3[m] = gelu_exact(a3[m]);
    }

    // Phase C: out[e, 4l..4l+3] = sum_m agg[d, 4l..4l+3, m] * T[s_e, m]
    for (int i = beg; i < end; i++) {
        int2 p = __ldg(&g_se[i]);
        const float4* Tp = (const float4*)(g_T + (size_t)p.x * MIX);
        float4 t0 = __ldg(Tp);
        float4 t1 = __ldg(Tp + 1);
        float t[8] = {t0.x, t0.y, t0.z, t0.w, t1.x, t1.y, t1.z, t1.w};
        float4 r = make_float4(0.f, 0.f, 0.f, 0.f);
        #pragma unroll
        for (int m = 0; m < 8; m++) {
            r.x = fmaf(a0[m], t[m], r.x);
            r.y = fmaf(a1[m], t[m], r.y);
            r.z = fmaf(a2[m], t[m], r.z);
            r.w = fmaf(a3[m], t[m], r.w);
        }
        *(float4*)(out + (size_t)p.y * HIDDEN + 4 * lane) = r;
    }
}

// Optional tail: src/dst appended as floats (full-tuple output case)
__global__ void tail_kernel(const void* __restrict__ ei, float* __restrict__ out, int E) {
    int e = blockIdx.x * blockDim.x + threadIdx.x;
    if (e >= E) return;
    int s, d;
    load_edge(ei, e, E, s, d);
    out[(size_t)E * HIDDEN + e] = (float)s;
    out[(size_t)E * HIDDEN + E + e] = (float)d;
}

extern "C" void kernel_launch(void* const* d_in, const int* in_sizes, int n_in,
                              void* d_out, int out_size) {
    const float* X  = (const float*)d_in[0];
    const float* WA = (const float*)d_in[1];
    const float* WB = (const float*)d_in[2];
    const void*  ei = d_in[3];

    int N = in_sizes[0] / HIDDEN;   // 10000
    int E = in_sizes[3] / 2;        // 320000
    float* out = (float*)d_out;

    prep_kernel<<<(N + 255) / 256, 256>>>((const unsigned int*)ei, N);
    hist_kernel<<<(E + 255) / 256, 256>>>(ei, E);
    scan_kernel<<<1, SCAN_T>>>(N);
    reorder_kernel<<<(E + 255) / 256, 256>>>(ei, E);
    compute_T_kernel<<<(N + 15) / 16, 128>>>(X, WA, WB, N);
    fused_kernel<<<(N + WPB - 1) / WPB, 32 * WPB>>>(X, out, N);

    if ((long long)out_size >= (long long)E * (HIDDEN + 2)) {
        tail_kernel<<<(E + 255) / 256, 256>>>(ei, out, E);
    }
}